// round 6
// baseline (speedup 1.0000x reference)
#include <cuda_runtime.h>
#include <cuda_fp16.h>
#include <mma.h>

using namespace nvcuda;

#define NMAX 50000
#define NPAD 50176          // 392*128 padding so GEMM tiles stay in-bounds
#define EMAX 1000000
#define HD   128

// ---------------- device scratch (no allocation allowed) ----------------
__device__ __align__(16) __half g_x[NPAD * HD];       // activations x~ (fp16; padding stays 0)
__device__ __align__(16) __half g_hs[NPAD * HD];      // messages hs = x~ @ W (fp16)
__device__ __align__(16) __half g_Bh[HD * HD];        // weight split hi
__device__ __align__(16) __half g_Bl[HD * HD];        // weight split lo
__device__ __align__(16) float  g_s1[NMAX * 3 + 4];
__device__ __align__(16) float  g_s2[NMAX * 3 + 4];
__device__ __align__(16) float  g_dis[NPAD];
__device__ __align__(16) int    g_deg[NMAX];
__device__ __align__(16) int    g_rowptr[NMAX + 1];
__device__ __align__(16) int    g_cursor[NMAX];
__device__ __align__(16) int    g_col[EMAX];
__device__ __align__(16) int    g_bsum[64];
__device__ int g_is64;

// ---------------- edge dtype detection (warp-parallel) ----------------
// int64 little-endian with values < 2^31 => odd 32-bit words of src region are 0.
__global__ void k_detect(const int* __restrict__ w, int E) {
    int lane = threadIdx.x & 31;
    int lim = 2 * E;
    int v = 0;
    for (int q = 0; q < 4; q++) {
        int idx = 1 + 2 * (lane + q * 32);
        if (idx < lim) v |= w[idx];
    }
    int any = __any_sync(0xFFFFFFFF, v != 0);
    if (lane == 0) g_is64 = any ? 0 : 1;
}

// degree count, decoding edges in place
__global__ void k_count(const int* __restrict__ w, int E) {
    int i = blockIdx.x * blockDim.x + threadIdx.x;
    if (i >= E) return;
    int d = g_is64 ? w[2 * E + 2 * i] : w[E + i];
    atomicAdd(&g_deg[d], 1);
}

// ---------------- CSR build ----------------
__global__ void k_scan1(int n) {
    __shared__ int s[1024];
    int i = blockIdx.x * 1024 + threadIdx.x;
    int v = (i < n) ? g_deg[i] : 0;
    if (i < n) g_dis[i] = rsqrtf((float)(v + 1));   // +1 self loop
    s[threadIdx.x] = v;
    __syncthreads();
    for (int off = 1; off < 1024; off <<= 1) {
        int t = (threadIdx.x >= off) ? s[threadIdx.x - off] : 0;
        __syncthreads();
        s[threadIdx.x] += t;
        __syncthreads();
    }
    if (i < n) g_rowptr[i + 1] = s[threadIdx.x];
    if (threadIdx.x == 1023) g_bsum[blockIdx.x] = s[1023];
}

__global__ void k_scan2(int nb) {
    if (threadIdx.x == 0 && blockIdx.x == 0) {
        int acc = 0;
        for (int b = 0; b < nb; b++) { int t = g_bsum[b]; g_bsum[b] = acc; acc += t; }
    }
}

// finalize rowptr + init cursor (fused)
__global__ void k_scan3(int n) {
    int i = blockIdx.x * 1024 + threadIdx.x;
    if (i < n) {
        int v = g_rowptr[i + 1] + g_bsum[blockIdx.x];
        g_rowptr[i + 1] = v;
        if (i + 1 < n) g_cursor[i + 1] = v;
    }
    if (i == 0) { g_rowptr[0] = 0; g_cursor[0] = 0; }
}

// CSR fill, decoding edges in place
__global__ void k_fill(const int* __restrict__ w, int E) {
    int i = blockIdx.x * blockDim.x + threadIdx.x;
    if (i >= E) return;
    int s, d;
    if (g_is64) {
        s = w[2 * i];
        d = w[2 * E + 2 * i];
    } else {
        s = w[i];
        d = w[E + i];
    }
    int p = atomicAdd(&g_cursor[d], 1);
    g_col[p] = s;
}

// ---------------- weight split: W (fp32) -> Bh + Bl (fp16) ----------------
__global__ void k_wsplit(const float* __restrict__ W) {
    int i = blockIdx.x * blockDim.x + threadIdx.x;
    if (i < HD * HD) {
        float v = W[i];
        __half h = __float2half_rn(v);
        g_Bh[i] = h;
        g_Bl[i] = __float2half_rn(v - __half2float(h));
    }
}

// ---------------- 3-wide ops ----------------
__global__ void k_scale3(const float* __restrict__ in, float* __restrict__ out, int n) {
    int i = blockIdx.x * blockDim.x + threadIdx.x;
    if (i < n * 3) out[i] = in[i] * g_dis[i / 3];
}

__global__ void k_agg3(const float* __restrict__ in, float* __restrict__ out,
                       const float* __restrict__ bias, int n) {
    int node = blockIdx.x * blockDim.x + threadIdx.x;
    if (node >= n) return;
    float a0 = in[node * 3 + 0], a1 = in[node * 3 + 1], a2 = in[node * 3 + 2];
    int s = g_rowptr[node], e = g_rowptr[node + 1];
    for (int i = s; i < e; i++) {
        int c = g_col[i];
        a0 += in[c * 3 + 0];
        a1 += in[c * 3 + 1];
        a2 += in[c * 3 + 2];
    }
    float d = g_dis[node];
    a0 *= d; a1 *= d; a2 *= d;
    if (bias) { a0 += bias[0]; a1 += bias[1]; a2 += bias[2]; }
    out[node * 3 + 0] = a0;
    out[node * 3 + 1] = a1;
    out[node * 3 + 2] = a2;
}

// x~ = dis * silu(t3 @ W0 + b0)  -> fp16
__global__ void k_gemm_in(const float* __restrict__ t3, const float* __restrict__ W0,
                          const float* __restrict__ b0, __half* __restrict__ out, int n) {
    __shared__ float sw[3 * HD];
    __shared__ float sb[HD];
    int t = threadIdx.x;
    for (int i = t; i < 3 * HD; i += blockDim.x) sw[i] = W0[i];
    if (t < HD) sb[t] = b0[t];
    __syncthreads();
    int gid = blockIdx.x * blockDim.x + t;
    if (gid < n * HD) {
        int node = gid >> 7, j = gid & 127;
        float p0 = t3[node * 3 + 0], p1 = t3[node * 3 + 1], p2 = t3[node * 3 + 2];
        float v = p0 * sw[j] + p1 * sw[HD + j] + p2 * sw[2 * HD + j] + sb[j];
        out[gid] = __float2half_rn(g_dis[node] * (v / (1.0f + __expf(-v))));
    }
}

// hs3 = x~ @ W4  (warp per node; dis already folded into x~)
__global__ void k_gemm_out(const __half* __restrict__ X, const float* __restrict__ W4,
                           float* __restrict__ Hs, int n) {
    int warp = (blockIdx.x * blockDim.x + threadIdx.x) >> 5;
    int lane = threadIdx.x & 31;
    if (warp >= n) return;
    uint2 u = ((const uint2*)X)[warp * 32 + lane];
    float2 p0 = __half22float2(*(__half2*)&u.x);
    float2 p1 = __half22float2(*(__half2*)&u.y);
    int k = lane * 4;
    float a0 = p0.x * W4[(k + 0) * 3 + 0] + p0.y * W4[(k + 1) * 3 + 0] +
               p1.x * W4[(k + 2) * 3 + 0] + p1.y * W4[(k + 3) * 3 + 0];
    float a1 = p0.x * W4[(k + 0) * 3 + 1] + p0.y * W4[(k + 1) * 3 + 1] +
               p1.x * W4[(k + 2) * 3 + 1] + p1.y * W4[(k + 3) * 3 + 1];
    float a2 = p0.x * W4[(k + 0) * 3 + 2] + p0.y * W4[(k + 1) * 3 + 2] +
               p1.x * W4[(k + 2) * 3 + 2] + p1.y * W4[(k + 3) * 3 + 2];
    for (int off = 16; off; off >>= 1) {
        a0 += __shfl_xor_sync(0xFFFFFFFF, a0, off);
        a1 += __shfl_xor_sync(0xFFFFFFFF, a1, off);
        a2 += __shfl_xor_sync(0xFFFFFFFF, a2, off);
    }
    if (lane == 0) {
        Hs[warp * 3 + 0] = a0;
        Hs[warp * 3 + 1] = a1;
        Hs[warp * 3 + 2] = a2;
    }
}

// ---------------- tensor-core hidden GEMM: hs = x~ @ (Bh+Bl), gmem-direct ----------------
// A is fp16 already (no split needed). Fragments loaded straight from gmem.
// No shared-memory staging, no mainloop __syncthreads.
__global__ __launch_bounds__(256) void k_gemm128_tc(const __half* __restrict__ X,
                                                    __half* __restrict__ Hout) {
    __shared__ __align__(16) float sOut[8][16 * 16];   // per-warp epilogue bounce

    int m0 = blockIdx.x * 128;
    int t = threadIdx.x;
    int warp = t >> 5;
    int lane = t & 31;
    int wm = warp >> 1;          // 0..3 : 32-row group
    int wn = warp & 1;           // 0..1 : 64-col group

    wmma::fragment<wmma::accumulator, 16, 16, 16, float> c[2][4];
#pragma unroll
    for (int i = 0; i < 2; i++)
#pragma unroll
        for (int j = 0; j < 4; j++) wmma::fill_fragment(c[i][j], 0.0f);

#pragma unroll
    for (int k0 = 0; k0 < HD; k0 += 16) {
        wmma::fragment<wmma::matrix_a, 16, 16, 16, __half, wmma::row_major> a[2];
        wmma::fragment<wmma::matrix_b, 16, 16, 16, __half, wmma::row_major> bH[4], bL[4];
#pragma unroll
        for (int i = 0; i < 2; i++)
            wmma::load_matrix_sync(a[i], X + (m0 + wm * 32 + i * 16) * HD + k0, HD);
#pragma unroll
        for (int j = 0; j < 4; j++) {
            wmma::load_matrix_sync(bH[j], g_Bh + k0 * HD + wn * 64 + j * 16, HD);
            wmma::load_matrix_sync(bL[j], g_Bl + k0 * HD + wn * 64 + j * 16, HD);
        }
#pragma unroll
        for (int i = 0; i < 2; i++)
#pragma unroll
            for (int j = 0; j < 4; j++) {
                wmma::mma_sync(c[i][j], a[i], bH[j], c[i][j]);
                wmma::mma_sync(c[i][j], a[i], bL[j], c[i][j]);
            }
    }

    // fp32 fragment -> fp16 gmem via per-warp smem bounce
#pragma unroll
    for (int i = 0; i < 2; i++)
#pragma unroll
        for (int j = 0; j < 4; j++) {
            wmma::store_matrix_sync(&sOut[warp][0], c[i][j], 16, wmma::mem_row_major);
            __syncwarp();
            int r = lane >> 1;                 // 0..15
            int c8 = (lane & 1) * 8;           // 0 or 8
            const float* srcp = &sOut[warp][r * 16 + c8];
            __half2 o[4];
#pragma unroll
            for (int q = 0; q < 4; q++)
                o[q] = __floats2half2_rn(srcp[2 * q], srcp[2 * q + 1]);
            __half* dst = Hout + (m0 + wm * 32 + i * 16 + r) * HD + wn * 64 + j * 16 + c8;
            *(uint4*)dst = *(uint4*)o;
            __syncwarp();
        }
}

// ---------------- 128-wide aggregation (fp16 in/out): warp per node ----------------
// x~out[n] = fp16( dis[n] * silu( dis[n]*(hs[n] + sum hs[src]) + b ) )
__global__ void k_agg128(const __half* __restrict__ hs, const float* __restrict__ bias,
                         __half* __restrict__ out, int n) {
    int warp = (blockIdx.x * blockDim.x + threadIdx.x) >> 5;
    int lane = threadIdx.x & 31;
    if (warp >= n) return;
    const uint2* hsv = (const uint2*)hs;       // 2x half2 = 4 features per lane
    float4 acc;
    {
        uint2 u = hsv[warp * 32 + lane];       // self loop
        float2 p0 = __half22float2(*(__half2*)&u.x);
        float2 p1 = __half22float2(*(__half2*)&u.y);
        acc = make_float4(p0.x, p0.y, p1.x, p1.y);
    }
    int s = g_rowptr[warp], e = g_rowptr[warp + 1];
    int i = s;
    for (; i + 4 <= e; i += 4) {
        int c0 = g_col[i], c1 = g_col[i + 1], c2 = g_col[i + 2], c3 = g_col[i + 3];
        uint2 u0 = hsv[c0 * 32 + lane];
        uint2 u1 = hsv[c1 * 32 + lane];
        uint2 u2 = hsv[c2 * 32 + lane];
        uint2 u3 = hsv[c3 * 32 + lane];
        float2 a0 = __half22float2(*(__half2*)&u0.x), b0 = __half22float2(*(__half2*)&u0.y);
        float2 a1 = __half22float2(*(__half2*)&u1.x), b1 = __half22float2(*(__half2*)&u1.y);
        float2 a2 = __half22float2(*(__half2*)&u2.x), b2 = __half22float2(*(__half2*)&u2.y);
        float2 a3 = __half22float2(*(__half2*)&u3.x), b3 = __half22float2(*(__half2*)&u3.y);
        acc.x += a0.x + a1.x + a2.x + a3.x;
        acc.y += a0.y + a1.y + a2.y + a3.y;
        acc.z += b0.x + b1.x + b2.x + b3.x;
        acc.w += b0.y + b1.y + b2.y + b3.y;
    }
    for (; i < e; i++) {
        int c = g_col[i];
        uint2 u = hsv[c * 32 + lane];
        float2 p0 = __half22float2(*(__half2*)&u.x);
        float2 p1 = __half22float2(*(__half2*)&u.y);
        acc.x += p0.x; acc.y += p0.y; acc.z += p1.x; acc.w += p1.y;
    }
    float d = g_dis[warp];
    float4 b = ((const float4*)bias)[lane];
    float4 r;
    r.x = acc.x * d + b.x;
    r.y = acc.y * d + b.y;
    r.z = acc.z * d + b.z;
    r.w = acc.w * d + b.w;
    r.x = d * (r.x / (1.0f + __expf(-r.x)));
    r.y = d * (r.y / (1.0f + __expf(-r.y)));
    r.z = d * (r.z / (1.0f + __expf(-r.z)));
    r.w = d * (r.w / (1.0f + __expf(-r.w)));
    __half2 o[2];
    o[0] = __floats2half2_rn(r.x, r.y);
    o[1] = __floats2half2_rn(r.z, r.w);
    ((uint2*)out)[warp * 32 + lane] = *(uint2*)o;
}

// ---------------- host launch ----------------
extern "C" void kernel_launch(void* const* d_in, const int* in_sizes, int n_in,
                              void* d_out, int out_size) {
    const float* pos = (const float*)d_in[0];
    const int* ei_words = (const int*)d_in[1];
    const float* W[5]; const float* B[5];
    for (int l = 0; l < 5; l++) {
        W[l] = (const float*)d_in[2 + 2 * l];
        B[l] = (const float*)d_in[3 + 2 * l];
    }
    int N = in_sizes[0] / 3;        // 50000
    int E = in_sizes[1] / 2;        // 1000000

    __half *xbuf, *hsbuf;
    float *s1, *s2;
    int* degp;
    cudaGetSymbolAddress((void**)&xbuf, g_x);
    cudaGetSymbolAddress((void**)&hsbuf, g_hs);
    cudaGetSymbolAddress((void**)&s1, g_s1);
    cudaGetSymbolAddress((void**)&s2, g_s2);
    cudaGetSymbolAddress((void**)&degp, g_deg);

    int NB = (N + 1023) / 1024;

    // edge decode + degrees
    k_detect<<<1, 32>>>(ei_words, E);
    cudaMemsetAsync(degp, 0, N * sizeof(int));
    k_count<<<(E + 255) / 256, 256>>>(ei_words, E);

    // CSR build
    k_scan1<<<NB, 1024>>>(N);
    k_scan2<<<1, 32>>>(NB);
    k_scan3<<<NB, 1024>>>(N);
    k_fill<<<(E + 255) / 256, 256>>>(ei_words, E);

    // layer 0: 3-wide aggregate then dense W0 (+bias, silu, dis fold) -> fp16 x~
    k_scale3<<<(3 * N + 255) / 256, 256>>>(pos, s1, N);
    k_agg3<<<(N + 255) / 256, 256>>>(s1, s2, nullptr, N);
    k_gemm_in<<<(N * HD + 255) / 256, 256>>>(s2, W[0], B[0], xbuf, N);

    // layers 1..3: weight split, TC GEMM (gmem-direct), fp16 aggregation
    int gemm_blocks = NPAD / 128;        // 392
    int agg_blocks = (N * 32 + 255) / 256;
    for (int l = 1; l <= 3; l++) {
        k_wsplit<<<(HD * HD + 255) / 256, 256>>>(W[l]);
        k_gemm128_tc<<<gemm_blocks, 256>>>(xbuf, hsbuf);
        k_agg128<<<agg_blocks, 256>>>(hsbuf, B[l], xbuf, N);
    }

    // layer 4: dense to 3-wide, then 3-wide aggregation + bias -> out
    k_gemm_out<<<agg_blocks, 256>>>(xbuf, W[4], s1, N);
    k_agg3<<<(N + 255) / 256, 256>>>(s1, (float*)d_out, B[4], N);
}

// round 7
// speedup vs baseline: 1.0341x; 1.0341x over previous
#include <cuda_runtime.h>
#include <cuda_fp16.h>
#include <mma.h>

using namespace nvcuda;

#define NMAX 50000
#define NPAD 50176          // 392*128 padding so GEMM tiles stay in-bounds
#define EMAX 1000000
#define HD   128

// ---------------- device scratch (no allocation allowed) ----------------
__device__ __align__(16) __half g_x[NPAD * HD];       // activations x~ (fp16; padding stays 0)
__device__ __align__(16) __half g_hs[NPAD * HD];      // messages hs = x~ @ W (fp16)
__device__ __align__(16) __half g_Bh3[3 * HD * HD];   // weight splits hi (layers 1..3)
__device__ __align__(16) __half g_Bl3[3 * HD * HD];   // weight splits lo
__device__ __align__(16) float  g_s1[NMAX * 3 + 4];
__device__ __align__(16) float  g_s2[NMAX * 3 + 4];
__device__ __align__(16) float  g_dis[NPAD];
__device__ __align__(16) int    g_deg[NMAX];
__device__ __align__(16) int    g_rowptr[NMAX + 1];
__device__ __align__(16) int    g_cursor[NMAX];
__device__ __align__(16) int    g_col[EMAX];
__device__ __align__(16) int    g_bsum[64];
__device__ int g_is64;

// ---------------- edge dtype detection (warp-parallel) ----------------
// int64 little-endian with values < 2^31 => odd 32-bit words of src region are 0.
__global__ void k_detect(const int* __restrict__ w, int E) {
    int lane = threadIdx.x & 31;
    int lim = 2 * E;
    int v = 0;
    for (int q = 0; q < 4; q++) {
        int idx = 1 + 2 * (lane + q * 32);
        if (idx < lim) v |= w[idx];
    }
    int any = __any_sync(0xFFFFFFFF, v != 0);
    if (lane == 0) g_is64 = any ? 0 : 1;
}

// degree count, decoding edges in place
__global__ void k_count(const int* __restrict__ w, int E) {
    int i = blockIdx.x * blockDim.x + threadIdx.x;
    if (i >= E) return;
    int d = g_is64 ? w[2 * E + 2 * i] : w[E + i];
    atomicAdd(&g_deg[d], 1);
}

// ---------------- CSR build ----------------
// block scan of degrees -> partial rowptr, block sums; also dis and s1 = pos*dis
__global__ void k_scan1(const float* __restrict__ pos, int n) {
    __shared__ int s[1024];
    int i = blockIdx.x * 1024 + threadIdx.x;
    int v = (i < n) ? g_deg[i] : 0;
    if (i < n) {
        float d = rsqrtf((float)(v + 1));   // +1 self loop
        g_dis[i] = d;
        g_s1[3 * i + 0] = pos[3 * i + 0] * d;
        g_s1[3 * i + 1] = pos[3 * i + 1] * d;
        g_s1[3 * i + 2] = pos[3 * i + 2] * d;
    }
    s[threadIdx.x] = v;
    __syncthreads();
    for (int off = 1; off < 1024; off <<= 1) {
        int t = (threadIdx.x >= off) ? s[threadIdx.x - off] : 0;
        __syncthreads();
        s[threadIdx.x] += t;
        __syncthreads();
    }
    if (i < n) g_rowptr[i + 1] = s[threadIdx.x];
    if (threadIdx.x == 1023) g_bsum[blockIdx.x] = s[1023];
}

// finalize rowptr + init cursor; block prefix computed inline by warp 0 (no scan2)
__global__ void k_scan3(int n) {
    __shared__ int s_off;
    if (threadIdx.x < 32) {
        int l = threadIdx.x;
        int bid = blockIdx.x;
        int v = (l < bid) ? g_bsum[l] : 0;
        if (l + 32 < bid) v += g_bsum[l + 32];
        for (int off = 16; off; off >>= 1) v += __shfl_xor_sync(0xFFFFFFFF, v, off);
        if (l == 0) s_off = v;
    }
    __syncthreads();
    int off = s_off;
    int i = blockIdx.x * 1024 + threadIdx.x;
    if (i < n) {
        int v = g_rowptr[i + 1] + off;
        g_rowptr[i + 1] = v;
        if (i + 1 < n) g_cursor[i + 1] = v;
    }
    if (i == 0) { g_rowptr[0] = 0; g_cursor[0] = 0; }
}

// CSR fill, decoding edges in place
__global__ void k_fill(const int* __restrict__ w, int E) {
    int i = blockIdx.x * blockDim.x + threadIdx.x;
    if (i >= E) return;
    int s, d;
    if (g_is64) {
        s = w[2 * i];
        d = w[2 * E + 2 * i];
    } else {
        s = w[i];
        d = w[E + i];
    }
    int p = atomicAdd(&g_cursor[d], 1);
    g_col[p] = s;
}

// ---------------- weight splits for layers 1..3 (one kernel) ----------------
__global__ void k_wsplit_all(const float* __restrict__ W1, const float* __restrict__ W2,
                             const float* __restrict__ W3) {
    int i = blockIdx.x * blockDim.x + threadIdx.x;
    if (i >= 3 * HD * HD) return;
    int l = i / (HD * HD), j = i - l * (HD * HD);
    const float* W = (l == 0) ? W1 : (l == 1) ? W2 : W3;
    float v = W[j];
    __half h = __float2half_rn(v);
    g_Bh3[i] = h;
    g_Bl3[i] = __float2half_rn(v - __half2float(h));
}

// ---------------- 3-wide ops ----------------
__global__ void k_agg3(const float* __restrict__ in, float* __restrict__ out,
                       const float* __restrict__ bias, int n) {
    int node = blockIdx.x * blockDim.x + threadIdx.x;
    if (node >= n) return;
    float a0 = in[node * 3 + 0], a1 = in[node * 3 + 1], a2 = in[node * 3 + 2];
    int s = g_rowptr[node], e = g_rowptr[node + 1];
    for (int i = s; i < e; i++) {
        int c = g_col[i];
        a0 += in[c * 3 + 0];
        a1 += in[c * 3 + 1];
        a2 += in[c * 3 + 2];
    }
    float d = g_dis[node];
    a0 *= d; a1 *= d; a2 *= d;
    if (bias) { a0 += bias[0]; a1 += bias[1]; a2 += bias[2]; }
    out[node * 3 + 0] = a0;
    out[node * 3 + 1] = a1;
    out[node * 3 + 2] = a2;
}

// x~ = dis * silu(t3 @ W0 + b0)  -> fp16
__global__ void k_gemm_in(const float* __restrict__ t3, const float* __restrict__ W0,
                          const float* __restrict__ b0, __half* __restrict__ out, int n) {
    __shared__ float sw[3 * HD];
    __shared__ float sb[HD];
    int t = threadIdx.x;
    for (int i = t; i < 3 * HD; i += blockDim.x) sw[i] = W0[i];
    if (t < HD) sb[t] = b0[t];
    __syncthreads();
    int gid = blockIdx.x * blockDim.x + t;
    if (gid < n * HD) {
        int node = gid >> 7, j = gid & 127;
        float p0 = t3[node * 3 + 0], p1 = t3[node * 3 + 1], p2 = t3[node * 3 + 2];
        float v = p0 * sw[j] + p1 * sw[HD + j] + p2 * sw[2 * HD + j] + sb[j];
        out[gid] = __float2half_rn(g_dis[node] * (v / (1.0f + __expf(-v))));
    }
}

// hs3 = x~ @ W4  (warp per node; dis already folded into x~)
__global__ void k_gemm_out(const __half* __restrict__ X, const float* __restrict__ W4,
                           float* __restrict__ Hs, int n) {
    int warp = (blockIdx.x * blockDim.x + threadIdx.x) >> 5;
    int lane = threadIdx.x & 31;
    if (warp >= n) return;
    uint2 u = ((const uint2*)X)[warp * 32 + lane];
    float2 p0 = __half22float2(*(__half2*)&u.x);
    float2 p1 = __half22float2(*(__half2*)&u.y);
    int k = lane * 4;
    float a0 = p0.x * W4[(k + 0) * 3 + 0] + p0.y * W4[(k + 1) * 3 + 0] +
               p1.x * W4[(k + 2) * 3 + 0] + p1.y * W4[(k + 3) * 3 + 0];
    float a1 = p0.x * W4[(k + 0) * 3 + 1] + p0.y * W4[(k + 1) * 3 + 1] +
               p1.x * W4[(k + 2) * 3 + 1] + p1.y * W4[(k + 3) * 3 + 1];
    float a2 = p0.x * W4[(k + 0) * 3 + 2] + p0.y * W4[(k + 1) * 3 + 2] +
               p1.x * W4[(k + 2) * 3 + 2] + p1.y * W4[(k + 3) * 3 + 2];
    for (int off = 16; off; off >>= 1) {
        a0 += __shfl_xor_sync(0xFFFFFFFF, a0, off);
        a1 += __shfl_xor_sync(0xFFFFFFFF, a1, off);
        a2 += __shfl_xor_sync(0xFFFFFFFF, a2, off);
    }
    if (lane == 0) {
        Hs[warp * 3 + 0] = a0;
        Hs[warp * 3 + 1] = a1;
        Hs[warp * 3 + 2] = a2;
    }
}

// ---------------- tensor-core hidden GEMM: hs = x~ @ (Bh+Bl), gmem-direct ----------------
__global__ __launch_bounds__(256) void k_gemm128_tc(const __half* __restrict__ X,
                                                    const __half* __restrict__ Bh,
                                                    const __half* __restrict__ Bl,
                                                    __half* __restrict__ Hout) {
    __shared__ __align__(16) float sOut[8][16 * 16];   // per-warp epilogue bounce

    int m0 = blockIdx.x * 128;
    int t = threadIdx.x;
    int warp = t >> 5;
    int lane = t & 31;
    int wm = warp >> 1;          // 0..3 : 32-row group
    int wn = warp & 1;           // 0..1 : 64-col group

    wmma::fragment<wmma::accumulator, 16, 16, 16, float> c[2][4];
#pragma unroll
    for (int i = 0; i < 2; i++)
#pragma unroll
        for (int j = 0; j < 4; j++) wmma::fill_fragment(c[i][j], 0.0f);

#pragma unroll
    for (int k0 = 0; k0 < HD; k0 += 16) {
        wmma::fragment<wmma::matrix_a, 16, 16, 16, __half, wmma::row_major> a[2];
        wmma::fragment<wmma::matrix_b, 16, 16, 16, __half, wmma::row_major> bH[4], bL[4];
#pragma unroll
        for (int i = 0; i < 2; i++)
            wmma::load_matrix_sync(a[i], X + (m0 + wm * 32 + i * 16) * HD + k0, HD);
#pragma unroll
        for (int j = 0; j < 4; j++) {
            wmma::load_matrix_sync(bH[j], Bh + k0 * HD + wn * 64 + j * 16, HD);
            wmma::load_matrix_sync(bL[j], Bl + k0 * HD + wn * 64 + j * 16, HD);
        }
#pragma unroll
        for (int i = 0; i < 2; i++)
#pragma unroll
            for (int j = 0; j < 4; j++) {
                wmma::mma_sync(c[i][j], a[i], bH[j], c[i][j]);
                wmma::mma_sync(c[i][j], a[i], bL[j], c[i][j]);
            }
    }

    // fp32 fragment -> fp16 gmem via per-warp smem bounce
#pragma unroll
    for (int i = 0; i < 2; i++)
#pragma unroll
        for (int j = 0; j < 4; j++) {
            wmma::store_matrix_sync(&sOut[warp][0], c[i][j], 16, wmma::mem_row_major);
            __syncwarp();
            int r = lane >> 1;                 // 0..15
            int c8 = (lane & 1) * 8;           // 0 or 8
            const float* srcp = &sOut[warp][r * 16 + c8];
            __half2 o[4];
#pragma unroll
            for (int q = 0; q < 4; q++)
                o[q] = __floats2half2_rn(srcp[2 * q], srcp[2 * q + 1]);
            __half* dst = Hout + (m0 + wm * 32 + i * 16 + r) * HD + wn * 64 + j * 16 + c8;
            *(uint4*)dst = *(uint4*)o;
            __syncwarp();
        }
}

// ---------------- 128-wide aggregation: 16 lanes per node, uint4 gathers ----------------
// x~out[n] = fp16( dis[n] * silu( dis[n]*(hs[n] + sum hs[src]) + b ) )
__global__ void k_agg128(const __half* __restrict__ hs, const float* __restrict__ bias,
                         __half* __restrict__ out, int n) {
    int gtid = blockIdx.x * blockDim.x + threadIdx.x;
    int node = gtid >> 4;              // 16 lanes per node
    int l16 = gtid & 15;               // this lane's 8 features: [l16*8, l16*8+8)
    if (node >= n) return;
    const uint4* hs4 = (const uint4*)hs;   // 8 halfs per uint4, 16 uint4 per row
    float acc[8];
    {
        uint4 u = hs4[node * 16 + l16];    // self loop
        __half2* hp = (__half2*)&u;
#pragma unroll
        for (int q = 0; q < 4; q++) {
            float2 f = __half22float2(hp[q]);
            acc[2 * q] = f.x; acc[2 * q + 1] = f.y;
        }
    }
    int s = g_rowptr[node], e = g_rowptr[node + 1];
    int i = s;
    for (; i + 4 <= e; i += 4) {
        int c0 = g_col[i], c1 = g_col[i + 1], c2 = g_col[i + 2], c3 = g_col[i + 3];
        uint4 v0 = hs4[c0 * 16 + l16];
        uint4 v1 = hs4[c1 * 16 + l16];
        uint4 v2 = hs4[c2 * 16 + l16];
        uint4 v3 = hs4[c3 * 16 + l16];
        __half2* p0 = (__half2*)&v0;
        __half2* p1 = (__half2*)&v1;
        __half2* p2 = (__half2*)&v2;
        __half2* p3 = (__half2*)&v3;
#pragma unroll
        for (int q = 0; q < 4; q++) {
            float2 f0 = __half22float2(p0[q]);
            float2 f1 = __half22float2(p1[q]);
            float2 f2 = __half22float2(p2[q]);
            float2 f3 = __half22float2(p3[q]);
            acc[2 * q]     += (f0.x + f1.x) + (f2.x + f3.x);
            acc[2 * q + 1] += (f0.y + f1.y) + (f2.y + f3.y);
        }
    }
    for (; i < e; i++) {
        int c = g_col[i];
        uint4 v = hs4[c * 16 + l16];
        __half2* p = (__half2*)&v;
#pragma unroll
        for (int q = 0; q < 4; q++) {
            float2 f = __half22float2(p[q]);
            acc[2 * q] += f.x; acc[2 * q + 1] += f.y;
        }
    }
    float d = g_dis[node];
    const float4* b4 = (const float4*)bias;
    float4 b0 = b4[l16 * 2], b1 = b4[l16 * 2 + 1];
    float bb[8] = {b0.x, b0.y, b0.z, b0.w, b1.x, b1.y, b1.z, b1.w};
    __half2 o[4];
#pragma unroll
    for (int q = 0; q < 4; q++) {
        float r0 = acc[2 * q] * d + bb[2 * q];
        float r1 = acc[2 * q + 1] * d + bb[2 * q + 1];
        r0 = d * (r0 / (1.0f + __expf(-r0)));
        r1 = d * (r1 / (1.0f + __expf(-r1)));
        o[q] = __floats2half2_rn(r0, r1);
    }
    ((uint4*)out)[node * 16 + l16] = *(uint4*)o;
}

// ---------------- host launch ----------------
extern "C" void kernel_launch(void* const* d_in, const int* in_sizes, int n_in,
                              void* d_out, int out_size) {
    const float* pos = (const float*)d_in[0];
    const int* ei_words = (const int*)d_in[1];
    const float* W[5]; const float* B[5];
    for (int l = 0; l < 5; l++) {
        W[l] = (const float*)d_in[2 + 2 * l];
        B[l] = (const float*)d_in[3 + 2 * l];
    }
    int N = in_sizes[0] / 3;        // 50000
    int E = in_sizes[1] / 2;        // 1000000

    __half *xbuf, *hsbuf, *bh3, *bl3;
    float *s1, *s2;
    int* degp;
    cudaGetSymbolAddress((void**)&xbuf, g_x);
    cudaGetSymbolAddress((void**)&hsbuf, g_hs);
    cudaGetSymbolAddress((void**)&bh3, g_Bh3);
    cudaGetSymbolAddress((void**)&bl3, g_Bl3);
    cudaGetSymbolAddress((void**)&s1, g_s1);
    cudaGetSymbolAddress((void**)&s2, g_s2);
    cudaGetSymbolAddress((void**)&degp, g_deg);

    int NB = (N + 1023) / 1024;

    // front matter: weight splits (off critical path), edge decode, degrees
    k_wsplit_all<<<(3 * HD * HD + 255) / 256, 256>>>(W[1], W[2], W[3]);
    k_detect<<<1, 32>>>(ei_words, E);
    cudaMemsetAsync(degp, 0, N * sizeof(int));
    k_count<<<(E + 255) / 256, 256>>>(ei_words, E);

    // CSR build (+ dis, s1 = pos*dis fused into scan1)
    k_scan1<<<NB, 1024>>>(pos, N);
    k_scan3<<<NB, 1024>>>(N);
    k_fill<<<(E + 255) / 256, 256>>>(ei_words, E);

    // layer 0: 3-wide aggregate then dense W0 (+bias, silu, dis fold) -> fp16 x~
    k_agg3<<<(N + 255) / 256, 256>>>(s1, s2, nullptr, N);
    k_gemm_in<<<(N * HD + 255) / 256, 256>>>(s2, W[0], B[0], xbuf, N);

    // layers 1..3: TC GEMM (pre-split weights) then fp16 aggregation
    int gemm_blocks = NPAD / 128;            // 392
    int agg_blocks = (N * 16 + 255) / 256;   // 16 lanes per node
    for (int l = 1; l <= 3; l++) {
        k_gemm128_tc<<<gemm_blocks, 256>>>(xbuf, bh3 + (l - 1) * HD * HD,
                                           bl3 + (l - 1) * HD * HD, hsbuf);
        k_agg128<<<agg_blocks, 256>>>(hsbuf, B[l], xbuf, N);
    }

    // layer 4: dense to 3-wide, then 3-wide aggregation + bias -> out
    k_gemm_out<<<(N * 32 + 255) / 256, 256>>>(xbuf, W[4], s1, N);
    k_agg3<<<(N + 255) / 256, 256>>>(s1, (float*)d_out, B[4], N);
}

// round 8
// speedup vs baseline: 1.0911x; 1.0551x over previous
#include <cuda_runtime.h>
#include <cuda_fp16.h>
#include <mma.h>

using namespace nvcuda;

#define NMAX 50000
#define NPAD 50176          // 392*128 padding so GEMM tiles stay in-bounds
#define EMAX 1000000
#define HD   128

// ---------------- device scratch (no allocation allowed) ----------------
__device__ __align__(16) __half g_x[NPAD * HD];       // activations x~ (fp16; padding stays 0)
__device__ __align__(16) __half g_hs[NPAD * HD];      // messages hs = x~ @ W (fp16)
__device__ __align__(16) __half g_Bh3[3 * HD * HD];   // weight splits hi (layers 1..3)
__device__ __align__(16) __half g_Bl3[3 * HD * HD];   // weight splits lo
__device__ __align__(16) float  g_s1[NMAX * 3 + 4];
__device__ __align__(16) float  g_dis[NPAD];
__device__ __align__(16) int    g_deg[NMAX];
__device__ __align__(16) int    g_rowptr[NMAX + 1];
__device__ __align__(16) int    g_cursor[NMAX];
__device__ __align__(16) int    g_col[EMAX];
__device__ __align__(16) int    g_bsum[64];

// ---------------- inline edge dtype detection ----------------
// int64 little-endian with node ids < 2^31 => odd 32-bit words of src region are 0.
// For int32 data these words are random node ids; P[all 4 zero] ~ (1/N)^4.
__device__ __forceinline__ int edges_is64(const int* __restrict__ w) {
    return (w[1] | w[3] | w[5] | w[7]) == 0;
}

// degree count, decoding edges in place
__global__ void k_count(const int* __restrict__ w, int E) {
    int i = blockIdx.x * blockDim.x + threadIdx.x;
    if (i >= E) return;
    int d = edges_is64(w) ? w[2 * E + 2 * i] : w[E + i];
    atomicAdd(&g_deg[d], 1);
}

// ---------------- CSR build ----------------
// block scan of degrees -> partial rowptr, block sums; also dis and s1 = pos*dis
__global__ void k_scan1(const float* __restrict__ pos, int n) {
    __shared__ int s[1024];
    int i = blockIdx.x * 1024 + threadIdx.x;
    int v = (i < n) ? g_deg[i] : 0;
    if (i < n) {
        float d = rsqrtf((float)(v + 1));   // +1 self loop
        g_dis[i] = d;
        g_s1[3 * i + 0] = pos[3 * i + 0] * d;
        g_s1[3 * i + 1] = pos[3 * i + 1] * d;
        g_s1[3 * i + 2] = pos[3 * i + 2] * d;
    }
    s[threadIdx.x] = v;
    __syncthreads();
    for (int off = 1; off < 1024; off <<= 1) {
        int t = (threadIdx.x >= off) ? s[threadIdx.x - off] : 0;
        __syncthreads();
        s[threadIdx.x] += t;
        __syncthreads();
    }
    if (i < n) g_rowptr[i + 1] = s[threadIdx.x];
    if (threadIdx.x == 1023) g_bsum[blockIdx.x] = s[1023];
}

// finalize rowptr + init cursor; block prefix computed inline by warp 0
__global__ void k_scan3(int n) {
    __shared__ int s_off;
    if (threadIdx.x < 32) {
        int l = threadIdx.x;
        int bid = blockIdx.x;
        int v = (l < bid) ? g_bsum[l] : 0;
        if (l + 32 < bid) v += g_bsum[l + 32];
        for (int off = 16; off; off >>= 1) v += __shfl_xor_sync(0xFFFFFFFF, v, off);
        if (l == 0) s_off = v;
    }
    __syncthreads();
    int off = s_off;
    int i = blockIdx.x * 1024 + threadIdx.x;
    if (i < n) {
        int v = g_rowptr[i + 1] + off;
        g_rowptr[i + 1] = v;
        if (i + 1 < n) g_cursor[i + 1] = v;
    }
    if (i == 0) { g_rowptr[0] = 0; g_cursor[0] = 0; }
}

// CSR fill, decoding edges in place
__global__ void k_fill(const int* __restrict__ w, int E) {
    int i = blockIdx.x * blockDim.x + threadIdx.x;
    if (i >= E) return;
    int s, d;
    if (edges_is64(w)) {
        s = w[2 * i];
        d = w[2 * E + 2 * i];
    } else {
        s = w[i];
        d = w[E + i];
    }
    int p = atomicAdd(&g_cursor[d], 1);
    g_col[p] = s;
}

// ---------------- weight splits for layers 1..3 (one kernel) ----------------
__global__ void k_wsplit_all(const float* __restrict__ W1, const float* __restrict__ W2,
                             const float* __restrict__ W3) {
    int i = blockIdx.x * blockDim.x + threadIdx.x;
    if (i >= 3 * HD * HD) return;
    int l = i / (HD * HD), j = i - l * (HD * HD);
    const float* W = (l == 0) ? W1 : (l == 1) ? W2 : W3;
    float v = W[j];
    __half h = __float2half_rn(v);
    g_Bh3[i] = h;
    g_Bl3[i] = __float2half_rn(v - __half2float(h));
}

// ---------------- fused layer 0: warp per node ----------------
// a = dis[n]*(s1[n] + sum s1[src]);  x~[n][j] = fp16(dis[n]*silu(a·W0[:,j]+b0[j]))
__global__ __launch_bounds__(256) void k_layer0(const float* __restrict__ s1,
                                                const float* __restrict__ W0,
                                                const float* __restrict__ b0,
                                                __half* __restrict__ out, int n) {
    __shared__ float sw[3 * HD];
    __shared__ float sb[HD];
    int t = threadIdx.x;
    for (int i = t; i < 3 * HD; i += 256) sw[i] = W0[i];
    if (t < HD) sb[t] = b0[t];
    __syncthreads();
    int warp = (blockIdx.x * 256 + t) >> 5;
    int lane = t & 31;
    if (warp >= n) return;
    int s = g_rowptr[warp], e = g_rowptr[warp + 1];
    float a0 = 0.f, a1 = 0.f, a2 = 0.f;
    for (int i = s + lane; i < e; i += 32) {
        int c = g_col[i];
        a0 += s1[3 * c + 0];
        a1 += s1[3 * c + 1];
        a2 += s1[3 * c + 2];
    }
    for (int off = 16; off; off >>= 1) {
        a0 += __shfl_xor_sync(0xFFFFFFFF, a0, off);
        a1 += __shfl_xor_sync(0xFFFFFFFF, a1, off);
        a2 += __shfl_xor_sync(0xFFFFFFFF, a2, off);
    }
    a0 += s1[3 * warp + 0];            // self loop
    a1 += s1[3 * warp + 1];
    a2 += s1[3 * warp + 2];
    float d = g_dis[warp];
    a0 *= d; a1 *= d; a2 *= d;
    __half2 o[2];
#pragma unroll
    for (int q = 0; q < 2; q++) {
        int j0 = lane * 4 + 2 * q;
        float v0 = a0 * sw[j0] + a1 * sw[HD + j0] + a2 * sw[2 * HD + j0] + sb[j0];
        float v1 = a0 * sw[j0 + 1] + a1 * sw[HD + j0 + 1] + a2 * sw[2 * HD + j0 + 1] + sb[j0 + 1];
        v0 = d * (v0 / (1.0f + __expf(-v0)));
        v1 = d * (v1 / (1.0f + __expf(-v1)));
        o[q] = __floats2half2_rn(v0, v1);
    }
    ((uint2*)out)[warp * 32 + lane] = *(uint2*)o;
}

// ---------------- final 3-wide ops ----------------
// hs3 = x~ @ W4  (warp per node; dis already folded into x~)
__global__ void k_gemm_out(const __half* __restrict__ X, const float* __restrict__ W4,
                           float* __restrict__ Hs, int n) {
    int warp = (blockIdx.x * blockDim.x + threadIdx.x) >> 5;
    int lane = threadIdx.x & 31;
    if (warp >= n) return;
    uint2 u = ((const uint2*)X)[warp * 32 + lane];
    float2 p0 = __half22float2(*(__half2*)&u.x);
    float2 p1 = __half22float2(*(__half2*)&u.y);
    int k = lane * 4;
    float a0 = p0.x * W4[(k + 0) * 3 + 0] + p0.y * W4[(k + 1) * 3 + 0] +
               p1.x * W4[(k + 2) * 3 + 0] + p1.y * W4[(k + 3) * 3 + 0];
    float a1 = p0.x * W4[(k + 0) * 3 + 1] + p0.y * W4[(k + 1) * 3 + 1] +
               p1.x * W4[(k + 2) * 3 + 1] + p1.y * W4[(k + 3) * 3 + 1];
    float a2 = p0.x * W4[(k + 0) * 3 + 2] + p0.y * W4[(k + 1) * 3 + 2] +
               p1.x * W4[(k + 2) * 3 + 2] + p1.y * W4[(k + 3) * 3 + 2];
    for (int off = 16; off; off >>= 1) {
        a0 += __shfl_xor_sync(0xFFFFFFFF, a0, off);
        a1 += __shfl_xor_sync(0xFFFFFFFF, a1, off);
        a2 += __shfl_xor_sync(0xFFFFFFFF, a2, off);
    }
    if (lane == 0) {
        Hs[warp * 3 + 0] = a0;
        Hs[warp * 3 + 1] = a1;
        Hs[warp * 3 + 2] = a2;
    }
}

// out[n][j] = dis[n]*(hs3[n][j] + sum hs3[src][j]) + b[j]
__global__ void k_agg3(const float* __restrict__ in, float* __restrict__ out,
                       const float* __restrict__ bias, int n) {
    int node = blockIdx.x * blockDim.x + threadIdx.x;
    if (node >= n) return;
    float a0 = in[node * 3 + 0], a1 = in[node * 3 + 1], a2 = in[node * 3 + 2];
    int s = g_rowptr[node], e = g_rowptr[node + 1];
    for (int i = s; i < e; i++) {
        int c = g_col[i];
        a0 += in[c * 3 + 0];
        a1 += in[c * 3 + 1];
        a2 += in[c * 3 + 2];
    }
    float d = g_dis[node];
    out[node * 3 + 0] = a0 * d + bias[0];
    out[node * 3 + 1] = a1 * d + bias[1];
    out[node * 3 + 2] = a2 * d + bias[2];
}

// ---------------- tensor-core hidden GEMM: hs = x~ @ (Bh+Bl), gmem-direct ----------------
__global__ __launch_bounds__(256) void k_gemm128_tc(const __half* __restrict__ X,
                                                    const __half* __restrict__ Bh,
                                                    const __half* __restrict__ Bl,
                                                    __half* __restrict__ Hout) {
    __shared__ __align__(16) float sOut[8][16 * 16];   // per-warp epilogue bounce

    int m0 = blockIdx.x * 128;
    int t = threadIdx.x;
    int warp = t >> 5;
    int lane = t & 31;
    int wm = warp >> 1;          // 0..3 : 32-row group
    int wn = warp & 1;           // 0..1 : 64-col group

    wmma::fragment<wmma::accumulator, 16, 16, 16, float> c[2][4];
#pragma unroll
    for (int i = 0; i < 2; i++)
#pragma unroll
        for (int j = 0; j < 4; j++) wmma::fill_fragment(c[i][j], 0.0f);

#pragma unroll
    for (int k0 = 0; k0 < HD; k0 += 16) {
        wmma::fragment<wmma::matrix_a, 16, 16, 16, __half, wmma::row_major> a[2];
        wmma::fragment<wmma::matrix_b, 16, 16, 16, __half, wmma::row_major> bH[4], bL[4];
#pragma unroll
        for (int i = 0; i < 2; i++)
            wmma::load_matrix_sync(a[i], X + (m0 + wm * 32 + i * 16) * HD + k0, HD);
#pragma unroll
        for (int j = 0; j < 4; j++) {
            wmma::load_matrix_sync(bH[j], Bh + k0 * HD + wn * 64 + j * 16, HD);
            wmma::load_matrix_sync(bL[j], Bl + k0 * HD + wn * 64 + j * 16, HD);
        }
#pragma unroll
        for (int i = 0; i < 2; i++)
#pragma unroll
            for (int j = 0; j < 4; j++) {
                wmma::mma_sync(c[i][j], a[i], bH[j], c[i][j]);
                wmma::mma_sync(c[i][j], a[i], bL[j], c[i][j]);
            }
    }

    // fp32 fragment -> fp16 gmem via per-warp smem bounce
#pragma unroll
    for (int i = 0; i < 2; i++)
#pragma unroll
        for (int j = 0; j < 4; j++) {
            wmma::store_matrix_sync(&sOut[warp][0], c[i][j], 16, wmma::mem_row_major);
            __syncwarp();
            int r = lane >> 1;                 // 0..15
            int c8 = (lane & 1) * 8;           // 0 or 8
            const float* srcp = &sOut[warp][r * 16 + c8];
            __half2 o[4];
#pragma unroll
            for (int q = 0; q < 4; q++)
                o[q] = __floats2half2_rn(srcp[2 * q], srcp[2 * q + 1]);
            __half* dst = Hout + (m0 + wm * 32 + i * 16 + r) * HD + wn * 64 + j * 16 + c8;
            *(uint4*)dst = *(uint4*)o;
            __syncwarp();
        }
}

// ---------------- 128-wide aggregation: 16 lanes per node ----------------
// Vector col loads (int4 per 4 edges) + pairwise HADD2 before float accumulate.
// x~out[n] = fp16( dis[n] * silu( dis[n]*(hs[n] + sum hs[src]) + b ) )
__global__ void k_agg128(const __half* __restrict__ hs, const float* __restrict__ bias,
                         __half* __restrict__ out, int n) {
    int gtid = blockIdx.x * blockDim.x + threadIdx.x;
    int node = gtid >> 4;              // 16 lanes per node
    int l16 = gtid & 15;               // this lane's 8 features: [l16*8, l16*8+8)
    if (node >= n) return;
    const uint4* hs4 = (const uint4*)hs;   // 8 halfs per uint4, 16 uint4 per row
    float acc[8];
    {
        uint4 u = hs4[node * 16 + l16];    // self loop
        __half2* hp = (__half2*)&u;
#pragma unroll
        for (int q = 0; q < 4; q++) {
            float2 f = __half22float2(hp[q]);
            acc[2 * q] = f.x; acc[2 * q + 1] = f.y;
        }
    }
    int s = g_rowptr[node], e = g_rowptr[node + 1];
    int i = s;
    // scalar head until 4-aligned index (int4 col loads need 16B alignment)
    int head = (s + 3) & ~3;
    if (head > e) head = e;
    for (; i < head; i++) {
        int c = g_col[i];
        uint4 v = hs4[c * 16 + l16];
        __half2* p = (__half2*)&v;
#pragma unroll
        for (int q = 0; q < 4; q++) {
            float2 f = __half22float2(p[q]);
            acc[2 * q] += f.x; acc[2 * q + 1] += f.y;
        }
    }
    // vectorized body: 4 edges per iter
    for (; i + 4 <= e; i += 4) {
        int4 cc = *(const int4*)(g_col + i);
        uint4 v0 = hs4[cc.x * 16 + l16];
        uint4 v1 = hs4[cc.y * 16 + l16];
        uint4 v2 = hs4[cc.z * 16 + l16];
        uint4 v3 = hs4[cc.w * 16 + l16];
        __half2* p0 = (__half2*)&v0;
        __half2* p1 = (__half2*)&v1;
        __half2* p2 = (__half2*)&v2;
        __half2* p3 = (__half2*)&v3;
#pragma unroll
        for (int q = 0; q < 4; q++) {
            __half2 t01 = __hadd2(p0[q], p1[q]);   // one fp16 rounding per pair
            __half2 t23 = __hadd2(p2[q], p3[q]);
            float2 f01 = __half22float2(t01);
            float2 f23 = __half22float2(t23);
            acc[2 * q]     += f01.x + f23.x;
            acc[2 * q + 1] += f01.y + f23.y;
        }
    }
    // scalar tail
    for (; i < e; i++) {
        int c = g_col[i];
        uint4 v = hs4[c * 16 + l16];
        __half2* p = (__half2*)&v;
#pragma unroll
        for (int q = 0; q < 4; q++) {
            float2 f = __half22float2(p[q]);
            acc[2 * q] += f.x; acc[2 * q + 1] += f.y;
        }
    }
    float d = g_dis[node];
    const float4* b4 = (const float4*)bias;
    float4 b0 = b4[l16 * 2], b1 = b4[l16 * 2 + 1];
    float bb[8] = {b0.x, b0.y, b0.z, b0.w, b1.x, b1.y, b1.z, b1.w};
    __half2 o[4];
#pragma unroll
    for (int q = 0; q < 4; q++) {
        float r0 = acc[2 * q] * d + bb[2 * q];
        float r1 = acc[2 * q + 1] * d + bb[2 * q + 1];
        r0 = d * (r0 / (1.0f + __expf(-r0)));
        r1 = d * (r1 / (1.0f + __expf(-r1)));
        o[q] = __floats2half2_rn(r0, r1);
    }
    ((uint4*)out)[node * 16 + l16] = *(uint4*)o;
}

// ---------------- host launch ----------------
extern "C" void kernel_launch(void* const* d_in, const int* in_sizes, int n_in,
                              void* d_out, int out_size) {
    const float* pos = (const float*)d_in[0];
    const int* ei_words = (const int*)d_in[1];
    const float* W[5]; const float* B[5];
    for (int l = 0; l < 5; l++) {
        W[l] = (const float*)d_in[2 + 2 * l];
        B[l] = (const float*)d_in[3 + 2 * l];
    }
    int N = in_sizes[0] / 3;        // 50000
    int E = in_sizes[1] / 2;        // 1000000

    __half *xbuf, *hsbuf, *bh3, *bl3;
    float *s1;
    int* degp;
    cudaGetSymbolAddress((void**)&xbuf, g_x);
    cudaGetSymbolAddress((void**)&hsbuf, g_hs);
    cudaGetSymbolAddress((void**)&bh3, g_Bh3);
    cudaGetSymbolAddress((void**)&bl3, g_Bl3);
    cudaGetSymbolAddress((void**)&s1, g_s1);
    cudaGetSymbolAddress((void**)&degp, g_deg);

    int NB = (N + 1023) / 1024;

    // front matter: weight splits, degree zero+count
    k_wsplit_all<<<(3 * HD * HD + 255) / 256, 256>>>(W[1], W[2], W[3]);
    cudaMemsetAsync(degp, 0, N * sizeof(int));
    k_count<<<(E + 255) / 256, 256>>>(ei_words, E);

    // CSR build (+ dis, s1 = pos*dis fused into scan1)
    k_scan1<<<NB, 1024>>>(pos, N);
    k_scan3<<<NB, 1024>>>(N);
    k_fill<<<(E + 255) / 256, 256>>>(ei_words, E);

    // layer 0 (fused 3-wide agg + dense W0 + bias + silu + dis fold) -> fp16 x~
    k_layer0<<<(N * 32 + 255) / 256, 256>>>(s1, W[0], B[0], xbuf, N);

    // layers 1..3: TC GEMM (pre-split weights) then fp16 aggregation
    int gemm_blocks = NPAD / 128;            // 392
    int agg_blocks = (N * 16 + 255) / 256;   // 16 lanes per node
    for (int l = 1; l <= 3; l++) {
        k_gemm128_tc<<<gemm_blocks, 256>>>(xbuf, bh3 + (l - 1) * HD * HD,
                                           bl3 + (l - 1) * HD * HD, hsbuf);
        k_agg128<<<agg_blocks, 256>>>(hsbuf, B[l], xbuf, N);
    }

    // layer 4: dense to 3-wide, then 3-wide aggregation + bias -> out
    k_gemm_out<<<(N * 32 + 255) / 256, 256>>>(xbuf, W[4], s1, N);
    k_agg3<<<(N + 255) / 256, 256>>>(s1, (float*)d_out, B[4], N);
}

// round 9
// speedup vs baseline: 1.1061x; 1.0138x over previous
#include <cuda_runtime.h>
#include <cuda_fp16.h>
#include <mma.h>

using namespace nvcuda;

#define NMAX 50000
#define NPAD 50176          // 392*128 padding so GEMM tiles stay in-bounds
#define EMAX 1000000
#define HD   128

// ---------------- device scratch (no allocation allowed) ----------------
__device__ __align__(16) __half g_x[NPAD * HD];       // activations x~ (fp16; padding stays 0)
__device__ __align__(16) __half g_hs[NPAD * HD];      // messages hs = x~ @ W (fp16)
__device__ __align__(16) __half g_Bh3[3 * HD * HD];   // weight splits hi (layers 1..3)
__device__ __align__(16) __half g_Bl3[3 * HD * HD];   // weight splits lo
__device__ __align__(16) float  g_s1[NMAX * 3 + 4];
__device__ __align__(16) float  g_dis[NPAD];
__device__ __align__(16) int    g_deg[NMAX];
__device__ __align__(16) int    g_rowptr[NMAX + 1];
__device__ __align__(16) int    g_cursor[NMAX];
__device__ __align__(16) int    g_col[EMAX];
__device__ __align__(16) int    g_bsum[64];
__device__ int g_ct_scan;     // grid-sync counters (reset every launch by k_init)
__device__ int g_ct_tail;

// ---------------- inline edge dtype detection ----------------
// int64 little-endian with node ids < 2^31 => odd 32-bit words of src region are 0.
__device__ __forceinline__ int edges_is64(const int* __restrict__ w) {
    return (w[1] | w[3] | w[5] | w[7]) == 0;
}

// ---------------- init: weight splits + deg zero + counter reset ----------------
__global__ void k_init(const float* __restrict__ W1, const float* __restrict__ W2,
                       const float* __restrict__ W3, int n) {
    int i = blockIdx.x * blockDim.x + threadIdx.x;
    if (i < 3 * HD * HD) {
        int l = i / (HD * HD), j = i - l * (HD * HD);
        const float* W = (l == 0) ? W1 : (l == 1) ? W2 : W3;
        float v = W[j];
        __half h = __float2half_rn(v);
        g_Bh3[i] = h;
        g_Bl3[i] = __float2half_rn(v - __half2float(h));
    }
    if (i < n) g_deg[i] = 0;
    if (i == 0) { g_ct_scan = 0; g_ct_tail = 0; }
}

// degree count, decoding edges in place
__global__ void k_count(const int* __restrict__ w, int E) {
    int i = blockIdx.x * blockDim.x + threadIdx.x;
    if (i >= E) return;
    int d = edges_is64(w) ? w[2 * E + 2 * i] : w[E + i];
    atomicAdd(&g_deg[d], 1);
}

// ---------------- fused single-pass scan (grid co-resident: 49 blocks) ----------
// deg -> rowptr/cursor (exclusive prefix), dis, s1 = pos*dis. Grid-sync via spin.
__global__ __launch_bounds__(1024) void k_scan(const float* __restrict__ pos, int n) {
    __shared__ int s[1024];
    __shared__ int s_off;
    int tid = threadIdx.x;
    int i = blockIdx.x * 1024 + tid;
    int v = (i < n) ? g_deg[i] : 0;
    if (i < n) {
        float d = rsqrtf((float)(v + 1));   // +1 self loop
        g_dis[i] = d;
        g_s1[3 * i + 0] = pos[3 * i + 0] * d;
        g_s1[3 * i + 1] = pos[3 * i + 1] * d;
        g_s1[3 * i + 2] = pos[3 * i + 2] * d;
    }
    s[tid] = v;
    __syncthreads();
    for (int off = 1; off < 1024; off <<= 1) {
        int t = (tid >= off) ? s[tid - off] : 0;
        __syncthreads();
        s[tid] += t;
        __syncthreads();
    }
    // release: publish block sum, arrive
    if (tid == 1023) {
        g_bsum[blockIdx.x] = s[1023];
        __threadfence();
        atomicAdd(&g_ct_scan, 1);
    }
    // acquire: spin until all blocks arrived
    if (tid == 0) {
        while (((volatile int*)&g_ct_scan)[0] < gridDim.x) {}
    }
    __syncthreads();
    __threadfence();
    // block-offset = sum of bsum[0..bid)
    if (tid < 32) {
        int l = tid, bid = blockIdx.x;
        int pv = (l < bid) ? g_bsum[l] : 0;
        if (l + 32 < bid) pv += g_bsum[l + 32];
        for (int off = 16; off; off >>= 1) pv += __shfl_xor_sync(0xFFFFFFFF, pv, off);
        if (l == 0) s_off = pv;
    }
    __syncthreads();
    int off = s_off;
    if (i < n) {
        int rv = s[tid] + off;
        g_rowptr[i + 1] = rv;
        if (i + 1 < n) g_cursor[i + 1] = rv;
    }
    if (i == 0) { g_rowptr[0] = 0; g_cursor[0] = 0; }
}

// CSR fill, decoding edges in place
__global__ void k_fill(const int* __restrict__ w, int E) {
    int i = blockIdx.x * blockDim.x + threadIdx.x;
    if (i >= E) return;
    int s, d;
    if (edges_is64(w)) {
        s = w[2 * i];
        d = w[2 * E + 2 * i];
    } else {
        s = w[i];
        d = w[E + i];
    }
    int p = atomicAdd(&g_cursor[d], 1);
    g_col[p] = s;
}

// ---------------- fused layer 0: warp per node ----------------
// a = dis[n]*(s1[n] + sum s1[src]);  x~[n][j] = fp16(dis[n]*silu(a·W0[:,j]+b0[j]))
__global__ __launch_bounds__(256) void k_layer0(const float* __restrict__ s1,
                                                const float* __restrict__ W0,
                                                const float* __restrict__ b0,
                                                __half* __restrict__ out, int n) {
    __shared__ float sw[3 * HD];
    __shared__ float sb[HD];
    int t = threadIdx.x;
    for (int i = t; i < 3 * HD; i += 256) sw[i] = W0[i];
    if (t < HD) sb[t] = b0[t];
    __syncthreads();
    int warp = (blockIdx.x * 256 + t) >> 5;
    int lane = t & 31;
    if (warp >= n) return;
    int s = g_rowptr[warp], e = g_rowptr[warp + 1];
    float a0 = 0.f, a1 = 0.f, a2 = 0.f;
    for (int i = s + lane; i < e; i += 32) {
        int c = g_col[i];
        a0 += s1[3 * c + 0];
        a1 += s1[3 * c + 1];
        a2 += s1[3 * c + 2];
    }
    for (int off = 16; off; off >>= 1) {
        a0 += __shfl_xor_sync(0xFFFFFFFF, a0, off);
        a1 += __shfl_xor_sync(0xFFFFFFFF, a1, off);
        a2 += __shfl_xor_sync(0xFFFFFFFF, a2, off);
    }
    a0 += s1[3 * warp + 0];            // self loop
    a1 += s1[3 * warp + 1];
    a2 += s1[3 * warp + 2];
    float d = g_dis[warp];
    a0 *= d; a1 *= d; a2 *= d;
    __half2 o[2];
#pragma unroll
    for (int q = 0; q < 2; q++) {
        int j0 = lane * 4 + 2 * q;
        float v0 = a0 * sw[j0] + a1 * sw[HD + j0] + a2 * sw[2 * HD + j0] + sb[j0];
        float v1 = a0 * sw[j0 + 1] + a1 * sw[HD + j0 + 1] + a2 * sw[2 * HD + j0 + 1] + sb[j0 + 1];
        v0 = d * (v0 / (1.0f + __expf(-v0)));
        v1 = d * (v1 / (1.0f + __expf(-v1)));
        o[q] = __floats2half2_rn(v0, v1);
    }
    ((uint2*)out)[warp * 32 + lane] = *(uint2*)o;
}

// ---------------- tensor-core hidden GEMM: hs = x~ @ (Bh+Bl), gmem-direct ----------------
__global__ __launch_bounds__(256) void k_gemm128_tc(const __half* __restrict__ X,
                                                    const __half* __restrict__ Bh,
                                                    const __half* __restrict__ Bl,
                                                    __half* __restrict__ Hout) {
    __shared__ __align__(16) float sOut[8][16 * 16];   // per-warp epilogue bounce

    int m0 = blockIdx.x * 128;
    int t = threadIdx.x;
    int warp = t >> 5;
    int lane = t & 31;
    int wm = warp >> 1;          // 0..3 : 32-row group
    int wn = warp & 1;           // 0..1 : 64-col group

    wmma::fragment<wmma::accumulator, 16, 16, 16, float> c[2][4];
#pragma unroll
    for (int i = 0; i < 2; i++)
#pragma unroll
        for (int j = 0; j < 4; j++) wmma::fill_fragment(c[i][j], 0.0f);

#pragma unroll
    for (int k0 = 0; k0 < HD; k0 += 16) {
        wmma::fragment<wmma::matrix_a, 16, 16, 16, __half, wmma::row_major> a[2];
        wmma::fragment<wmma::matrix_b, 16, 16, 16, __half, wmma::row_major> bH[4], bL[4];
#pragma unroll
        for (int i = 0; i < 2; i++)
            wmma::load_matrix_sync(a[i], X + (m0 + wm * 32 + i * 16) * HD + k0, HD);
#pragma unroll
        for (int j = 0; j < 4; j++) {
            wmma::load_matrix_sync(bH[j], Bh + k0 * HD + wn * 64 + j * 16, HD);
            wmma::load_matrix_sync(bL[j], Bl + k0 * HD + wn * 64 + j * 16, HD);
        }
#pragma unroll
        for (int i = 0; i < 2; i++)
#pragma unroll
            for (int j = 0; j < 4; j++) {
                wmma::mma_sync(c[i][j], a[i], bH[j], c[i][j]);
                wmma::mma_sync(c[i][j], a[i], bL[j], c[i][j]);
            }
    }

    // fp32 fragment -> fp16 gmem via per-warp smem bounce
#pragma unroll
    for (int i = 0; i < 2; i++)
#pragma unroll
        for (int j = 0; j < 4; j++) {
            wmma::store_matrix_sync(&sOut[warp][0], c[i][j], 16, wmma::mem_row_major);
            __syncwarp();
            int r = lane >> 1;                 // 0..15
            int c8 = (lane & 1) * 8;           // 0 or 8
            const float* srcp = &sOut[warp][r * 16 + c8];
            __half2 o[4];
#pragma unroll
            for (int q = 0; q < 4; q++)
                o[q] = __floats2half2_rn(srcp[2 * q], srcp[2 * q + 1]);
            __half* dst = Hout + (m0 + wm * 32 + i * 16 + r) * HD + wn * 64 + j * 16 + c8;
            *(uint4*)dst = *(uint4*)o;
            __syncwarp();
        }
}

// ---------------- 128-wide aggregation: 16 lanes per node, 8-edge unroll ----------------
// x~out[n] = fp16( dis[n] * silu( dis[n]*(hs[n] + sum hs[src]) + b ) )
__global__ void k_agg128(const __half* __restrict__ hs, const float* __restrict__ bias,
                         __half* __restrict__ out, int n) {
    int gtid = blockIdx.x * blockDim.x + threadIdx.x;
    int node = gtid >> 4;              // 16 lanes per node
    int l16 = gtid & 15;               // this lane's 8 features: [l16*8, l16*8+8)
    if (node >= n) return;
    const uint4* hs4 = (const uint4*)hs;   // 8 halfs per uint4, 16 uint4 per row
    float acc[8];
    {
        uint4 u = hs4[node * 16 + l16];    // self loop
        __half2* hp = (__half2*)&u;
#pragma unroll
        for (int q = 0; q < 4; q++) {
            float2 f = __half22float2(hp[q]);
            acc[2 * q] = f.x; acc[2 * q + 1] = f.y;
        }
    }
    int s = g_rowptr[node], e = g_rowptr[node + 1];
    int i = s;
    // scalar head until 4-aligned index (int4 col loads need 16B alignment)
    int head = (s + 3) & ~3;
    if (head > e) head = e;
    for (; i < head; i++) {
        int c = g_col[i];
        uint4 v = hs4[c * 16 + l16];
        __half2* p = (__half2*)&v;
#pragma unroll
        for (int q = 0; q < 4; q++) {
            float2 f = __half22float2(p[q]);
            acc[2 * q] += f.x; acc[2 * q + 1] += f.y;
        }
    }
    // vectorized body: 8 edges per iter (8 outstanding 16B gathers)
    for (; i + 8 <= e; i += 8) {
        int4 ca = *(const int4*)(g_col + i);
        int4 cb = *(const int4*)(g_col + i + 4);
        uint4 v0 = hs4[ca.x * 16 + l16];
        uint4 v1 = hs4[ca.y * 16 + l16];
        uint4 v2 = hs4[ca.z * 16 + l16];
        uint4 v3 = hs4[ca.w * 16 + l16];
        uint4 v4 = hs4[cb.x * 16 + l16];
        uint4 v5 = hs4[cb.y * 16 + l16];
        uint4 v6 = hs4[cb.z * 16 + l16];
        uint4 v7 = hs4[cb.w * 16 + l16];
        __half2* p0 = (__half2*)&v0; __half2* p1 = (__half2*)&v1;
        __half2* p2 = (__half2*)&v2; __half2* p3 = (__half2*)&v3;
        __half2* p4 = (__half2*)&v4; __half2* p5 = (__half2*)&v5;
        __half2* p6 = (__half2*)&v6; __half2* p7 = (__half2*)&v7;
#pragma unroll
        for (int q = 0; q < 4; q++) {
            __half2 t01 = __hadd2(p0[q], p1[q]);   // one fp16 rounding per pair
            __half2 t23 = __hadd2(p2[q], p3[q]);
            __half2 t45 = __hadd2(p4[q], p5[q]);
            __half2 t67 = __hadd2(p6[q], p7[q]);
            float2 f01 = __half22float2(t01);
            float2 f23 = __half22float2(t23);
            float2 f45 = __half22float2(t45);
            float2 f67 = __half22float2(t67);
            acc[2 * q]     += (f01.x + f23.x) + (f45.x + f67.x);
            acc[2 * q + 1] += (f01.y + f23.y) + (f45.y + f67.y);
        }
    }
    // 4-edge step
    for (; i + 4 <= e; i += 4) {
        int4 cc = *(const int4*)(g_col + i);
        uint4 v0 = hs4[cc.x * 16 + l16];
        uint4 v1 = hs4[cc.y * 16 + l16];
        uint4 v2 = hs4[cc.z * 16 + l16];
        uint4 v3 = hs4[cc.w * 16 + l16];
        __half2* p0 = (__half2*)&v0; __half2* p1 = (__half2*)&v1;
        __half2* p2 = (__half2*)&v2; __half2* p3 = (__half2*)&v3;
#pragma unroll
        for (int q = 0; q < 4; q++) {
            __half2 t01 = __hadd2(p0[q], p1[q]);
            __half2 t23 = __hadd2(p2[q], p3[q]);
            float2 f01 = __half22float2(t01);
            float2 f23 = __half22float2(t23);
            acc[2 * q]     += f01.x + f23.x;
            acc[2 * q + 1] += f01.y + f23.y;
        }
    }
    // scalar tail
    for (; i < e; i++) {
        int c = g_col[i];
        uint4 v = hs4[c * 16 + l16];
        __half2* p = (__half2*)&v;
#pragma unroll
        for (int q = 0; q < 4; q++) {
            float2 f = __half22float2(p[q]);
            acc[2 * q] += f.x; acc[2 * q + 1] += f.y;
        }
    }
    float d = g_dis[node];
    const float4* b4 = (const float4*)bias;
    float4 b0 = b4[l16 * 2], b1 = b4[l16 * 2 + 1];
    float bb[8] = {b0.x, b0.y, b0.z, b0.w, b1.x, b1.y, b1.z, b1.w};
    __half2 o[4];
#pragma unroll
    for (int q = 0; q < 4; q++) {
        float r0 = acc[2 * q] * d + bb[2 * q];
        float r1 = acc[2 * q + 1] * d + bb[2 * q + 1];
        r0 = d * (r0 / (1.0f + __expf(-r0)));
        r1 = d * (r1 / (1.0f + __expf(-r1)));
        o[q] = __floats2half2_rn(r0, r1);
    }
    ((uint4*)out)[node * 16 + l16] = *(uint4*)o;
}

// ---------------- fused tail: hs3 = x~ @ W4, grid-sync, 3-wide agg -> out ---------
// Persistent grid of 592 blocks (4/SM on 148 SMs — co-resident by construction).
#define TAIL_BLOCKS 592
__global__ __launch_bounds__(256) void k_tail(const __half* __restrict__ X,
                                              const float* __restrict__ W4,
                                              const float* __restrict__ bias,
                                              float* __restrict__ s1,
                                              float* __restrict__ out, int n) {
    int t = threadIdx.x;
    int lane = t & 31;
    int nwarps = TAIL_BLOCKS * 8;
    // phase 1: warp per node, hs3 = x~ @ W4 -> s1
    for (int node = (blockIdx.x * 256 + t) >> 5; node < n; node += nwarps) {
        uint2 u = ((const uint2*)X)[node * 32 + lane];
        float2 p0 = __half22float2(*(__half2*)&u.x);
        float2 p1 = __half22float2(*(__half2*)&u.y);
        int k = lane * 4;
        float a0 = p0.x * W4[(k + 0) * 3 + 0] + p0.y * W4[(k + 1) * 3 + 0] +
                   p1.x * W4[(k + 2) * 3 + 0] + p1.y * W4[(k + 3) * 3 + 0];
        float a1 = p0.x * W4[(k + 0) * 3 + 1] + p0.y * W4[(k + 1) * 3 + 1] +
                   p1.x * W4[(k + 2) * 3 + 1] + p1.y * W4[(k + 3) * 3 + 1];
        float a2 = p0.x * W4[(k + 0) * 3 + 2] + p0.y * W4[(k + 1) * 3 + 2] +
                   p1.x * W4[(k + 2) * 3 + 2] + p1.y * W4[(k + 3) * 3 + 2];
        for (int off = 16; off; off >>= 1) {
            a0 += __shfl_xor_sync(0xFFFFFFFF, a0, off);
            a1 += __shfl_xor_sync(0xFFFFFFFF, a1, off);
            a2 += __shfl_xor_sync(0xFFFFFFFF, a2, off);
        }
        if (lane == 0) {
            s1[node * 3 + 0] = a0;
            s1[node * 3 + 1] = a1;
            s1[node * 3 + 2] = a2;
        }
    }
    // grid sync (release/acquire)
    __syncthreads();
    if (t == 0) {
        __threadfence();
        atomicAdd(&g_ct_tail, 1);
        while (((volatile int*)&g_ct_tail)[0] < TAIL_BLOCKS) {}
    }
    __syncthreads();
    __threadfence();
    // phase 2: thread per node, 3-wide aggregate + bias -> out
    float bb0 = bias[0], bb1 = bias[1], bb2 = bias[2];
    for (int node = blockIdx.x * 256 + t; node < n; node += TAIL_BLOCKS * 256) {
        float a0 = s1[node * 3 + 0], a1 = s1[node * 3 + 1], a2 = s1[node * 3 + 2];
        int s = g_rowptr[node], e = g_rowptr[node + 1];
        for (int i = s; i < e; i++) {
            int c = g_col[i];
            a0 += s1[3 * c + 0];
            a1 += s1[3 * c + 1];
            a2 += s1[3 * c + 2];
        }
        float d = g_dis[node];
        out[node * 3 + 0] = a0 * d + bb0;
        out[node * 3 + 1] = a1 * d + bb1;
        out[node * 3 + 2] = a2 * d + bb2;
    }
}

// ---------------- host launch ----------------
extern "C" void kernel_launch(void* const* d_in, const int* in_sizes, int n_in,
                              void* d_out, int out_size) {
    const float* pos = (const float*)d_in[0];
    const int* ei_words = (const int*)d_in[1];
    const float* W[5]; const float* B[5];
    for (int l = 0; l < 5; l++) {
        W[l] = (const float*)d_in[2 + 2 * l];
        B[l] = (const float*)d_in[3 + 2 * l];
    }
    int N = in_sizes[0] / 3;        // 50000
    int E = in_sizes[1] / 2;        // 1000000

    __half *xbuf, *hsbuf, *bh3, *bl3;
    float *s1;
    cudaGetSymbolAddress((void**)&xbuf, g_x);
    cudaGetSymbolAddress((void**)&hsbuf, g_hs);
    cudaGetSymbolAddress((void**)&bh3, g_Bh3);
    cudaGetSymbolAddress((void**)&bl3, g_Bl3);
    cudaGetSymbolAddress((void**)&s1, g_s1);

    int NB = (N + 1023) / 1024;     // 49

    // init (wsplit + deg zero + counters), degree count
    k_init<<<(NPAD + 255) / 256, 256>>>(W[1], W[2], W[3], N);
    k_count<<<(E + 255) / 256, 256>>>(ei_words, E);

    // fused scan (rowptr/cursor/dis/s1), CSR fill
    k_scan<<<NB, 1024>>>(pos, N);
    k_fill<<<(E + 255) / 256, 256>>>(ei_words, E);

    // layer 0 (fused 3-wide agg + dense W0 + bias + silu + dis fold) -> fp16 x~
    k_layer0<<<(N * 32 + 255) / 256, 256>>>(s1, W[0], B[0], xbuf, N);

    // layers 1..3: TC GEMM (pre-split weights) then fp16 aggregation
    int gemm_blocks = NPAD / 128;            // 392
    int agg_blocks = (N * 16 + 255) / 256;   // 16 lanes per node
    for (int l = 1; l <= 3; l++) {
        k_gemm128_tc<<<gemm_blocks, 256>>>(xbuf, bh3 + (l - 1) * HD * HD,
                                           bl3 + (l - 1) * HD * HD, hsbuf);
        k_agg128<<<agg_blocks, 256>>>(hsbuf, B[l], xbuf, N);
    }

    // fused tail: hs3 GEMM + grid sync + 3-wide aggregation -> out
    k_tail<<<TAIL_BLOCKS, 256>>>(xbuf, W[4], B[4], s1, (float*)d_out, N);
}